// round 12
// baseline (speedup 1.0000x reference)
#include <cuda_runtime.h>
#include <math.h>

// ---------------- Config ----------------
#define BB     8
#define CC     3
#define HH     384
#define WW     384
#define PP     16
#define DD     768
#define NHH    12
#define MLPD   3072
#define LL     12
#define NCLS   1000
#define NPAT   576
#define NTOK   577
#define HDIM   64
#define MTOK   (BB*NTOK)    // 4616
#define MPAD   4736         // 37*128
#define MPATCH (BB*NPAT)    // 4608 = 36*128

// ---------------- Scratch (device globals; .bss zero-init) ----------------
__device__ float g_t  [MPATCH*DD];
__device__ float g_emb[MPATCH*DD];
__device__ float g_h  [MPAD*DD];
__device__ float g_y  [MPAD*DD];
__device__ float g_q  [MPAD*DD];
__device__ float g_k  [MPAD*DD];
__device__ float g_v  [MPAD*DD];
__device__ float g_ao [MPAD*DD];
__device__ float g_mlp[MPAD*MLPD];
__device__ float g_cls[BB*DD];

// ---------------- Patch gather (faithful batch-mixing flatten) ----------------
__global__ void patch_k(const float* __restrict__ x, float* __restrict__ t) {
    int idx = blockIdx.x * 256 + threadIdx.x;
    if (idx >= MPATCH * DD) return;
    int p1  = idx / 221184;          // B*C*GH*GW*P
    int rem = idx % 221184;
    int b   = rem / 27648;  rem %= 27648;
    int c   = rem / 9216;   rem %= 9216;
    int gh  = rem / 384;    rem %= 384;
    int gw  = rem / 16;
    int p2  = rem % 16;
    t[idx] = x[(((b*CC + c)*HH) + gh*PP + p1) * WW + gw*PP + p2];
}

// ---------------- Assemble: CLS + pos_emb ----------------
__global__ void assemble_k(const float* __restrict__ emb, const float* __restrict__ cls_emb,
                           const float* __restrict__ pos, float* __restrict__ h) {
    int idx = blockIdx.x * 256 + threadIdx.x;
    if (idx >= BB * NTOK * DD) return;
    int d = idx % DD;
    int n = (idx / DD) % NTOK;
    int b = idx / (DD * NTOK);
    float val = (n == 0) ? cls_emb[d] : emb[((size_t)b*NPAT + (n-1))*DD + d];
    h[idx] = val + pos[n*DD + d];
}

// ---------------- TF32 tensor-core GEMM (double-buffered) ----------------
#define APAD 20
#define BPAD 136

__device__ __forceinline__ unsigned f2tf32(float x) {
    unsigned u;
    asm("cvt.rna.tf32.f32 %0, %1;" : "=r"(u) : "f"(x));
    return u;
}

__device__ __forceinline__ void mma_tf32(float* d, const unsigned* a, const unsigned* b) {
    asm volatile(
        "mma.sync.aligned.m16n8k8.row.col.f32.tf32.tf32.f32 "
        "{%0,%1,%2,%3}, {%4,%5,%6,%7}, {%8,%9}, {%0,%1,%2,%3};"
        : "+f"(d[0]), "+f"(d[1]), "+f"(d[2]), "+f"(d[3])
        : "r"(a[0]), "r"(a[1]), "r"(a[2]), "r"(a[3]), "r"(b[0]), "r"(b[1]));
}

__global__ void __launch_bounds__(256, 2)
gemm_tf32_k(const float* __restrict__ A, const float* __restrict__ W,
            const float* __restrict__ bias, float* __restrict__ C,
            int M, int N, int K, int mode) {
    __shared__ unsigned As[2][128 * APAD];
    __shared__ unsigned Bs[2][16 * BPAD];

    const int tid  = threadIdx.x;
    const int lane = tid & 31;
    const int warp = tid >> 5;
    const int wm   = warp & 1;
    const int wn   = warp >> 1;
    const int gid  = lane >> 2;
    const int tig  = lane & 3;
    const int row0 = blockIdx.y * 128;
    const int col0 = blockIdx.x * 128;

    // per-thread load coordinates
    const int ar  = tid >> 2;            // 0..63 (x2 halves)
    const int ac4 = (tid & 3) << 2;      // 0,4,8,12
    const int bk_ = tid >> 5;            // 0..7 (x2 halves)
    const int bn4 = (tid & 31) << 2;     // 0..124

    float acc[4][4][4];
#pragma unroll
    for (int i = 0; i < 4; i++)
#pragma unroll
        for (int j = 0; j < 4; j++)
#pragma unroll
            for (int c = 0; c < 4; c++) acc[i][j][c] = 0.f;

    // preload tile 0 into buffer 0
    {
#pragma unroll
        for (int it = 0; it < 2; it++) {
            int r = ar + it * 64;
            float4 v = *reinterpret_cast<const float4*>(&A[(size_t)(row0 + r) * K + ac4]);
            unsigned* dst = &As[0][r * APAD + ac4];
            dst[0] = f2tf32(v.x); dst[1] = f2tf32(v.y);
            dst[2] = f2tf32(v.z); dst[3] = f2tf32(v.w);
        }
#pragma unroll
        for (int it = 0; it < 2; it++) {
            int kk = bk_ + it * 8;
            float4 v = *reinterpret_cast<const float4*>(&W[(size_t)kk * N + col0 + bn4]);
            unsigned* dst = &Bs[0][kk * BPAD + bn4];
            dst[0] = f2tf32(v.x); dst[1] = f2tf32(v.y);
            dst[2] = f2tf32(v.z); dst[3] = f2tf32(v.w);
        }
    }
    __syncthreads();

    int cur = 0;
    for (int k0 = 0; k0 < K; k0 += 16) {
        const bool has_next = (k0 + 16) < K;
        float4 pa[2], pb[2];
        if (has_next) {
            const int kn = k0 + 16;
#pragma unroll
            for (int it = 0; it < 2; it++) {
                int r = ar + it * 64;
                pa[it] = *reinterpret_cast<const float4*>(&A[(size_t)(row0 + r) * K + kn + ac4]);
            }
#pragma unroll
            for (int it = 0; it < 2; it++) {
                int kk = bk_ + it * 8;
                pb[it] = *reinterpret_cast<const float4*>(&W[(size_t)(kn + kk) * N + col0 + bn4]);
            }
        }

        // compute on current buffer
        const unsigned* Asc = As[cur];
        const unsigned* Bsc = Bs[cur];
#pragma unroll
        for (int ks = 0; ks < 16; ks += 8) {
            unsigned af[4][4], bf[4][2];
#pragma unroll
            for (int mt = 0; mt < 4; mt++) {
                int r = wm * 64 + mt * 16 + gid;
                af[mt][0] = Asc[(r    ) * APAD + ks + tig    ];
                af[mt][1] = Asc[(r + 8) * APAD + ks + tig    ];
                af[mt][2] = Asc[(r    ) * APAD + ks + tig + 4];
                af[mt][3] = Asc[(r + 8) * APAD + ks + tig + 4];
            }
#pragma unroll
            for (int nt = 0; nt < 4; nt++) {
                int n = wn * 32 + nt * 8 + gid;
                bf[nt][0] = Bsc[(ks + tig    ) * BPAD + n];
                bf[nt][1] = Bsc[(ks + tig + 4) * BPAD + n];
            }
#pragma unroll
            for (int mt = 0; mt < 4; mt++)
#pragma unroll
                for (int nt = 0; nt < 4; nt++)
                    mma_tf32(acc[mt][nt], af[mt], bf[nt]);
        }

        if (has_next) {
            const int nxt = cur ^ 1;
#pragma unroll
            for (int it = 0; it < 2; it++) {
                int r = ar + it * 64;
                unsigned* dst = &As[nxt][r * APAD + ac4];
                dst[0] = f2tf32(pa[it].x); dst[1] = f2tf32(pa[it].y);
                dst[2] = f2tf32(pa[it].z); dst[3] = f2tf32(pa[it].w);
            }
#pragma unroll
            for (int it = 0; it < 2; it++) {
                int kk = bk_ + it * 8;
                unsigned* dst = &Bs[nxt][kk * BPAD + bn4];
                dst[0] = f2tf32(pb[it].x); dst[1] = f2tf32(pb[it].y);
                dst[2] = f2tf32(pb[it].z); dst[3] = f2tf32(pb[it].w);
            }
            __syncthreads();
            cur = nxt;
        }
    }

    // epilogue
#pragma unroll
    for (int mt = 0; mt < 4; mt++) {
#pragma unroll
        for (int nt = 0; nt < 4; nt++) {
#pragma unroll
            for (int c = 0; c < 4; c++) {
                int r   = row0 + wm * 64 + mt * 16 + gid + ((c >> 1) << 3);
                int col = col0 + wn * 32 + nt * 8 + tig * 2 + (c & 1);
                if (r >= M) continue;
                float v = acc[mt][nt][c] + bias[col];
                if (mode == 1)      v += C[(size_t)r * N + col];
                else if (mode == 2) v = 0.5f * v * (1.0f + erff(v * 0.70710678118654752f));
                C[(size_t)r * N + col] = v;
            }
        }
    }
}

// ---------------- LayerNorm (shuffle reductions) ----------------
__global__ void ln_k(const float* __restrict__ in, float* __restrict__ out,
                     const float* __restrict__ g, const float* __restrict__ b,
                     long in_stride) {
    const int row = blockIdx.x;
    const float* x = in + (size_t)row * in_stride;
    float* o = out + (size_t)row * DD;
    __shared__ float ws[8];
    const int tid  = threadIdx.x;
    const int lane = tid & 31;
    const int warp = tid >> 5;

    float xr[3];
    float s = 0.f;
#pragma unroll
    for (int t = 0; t < 3; t++) { xr[t] = x[tid + t * 256]; s += xr[t]; }
#pragma unroll
    for (int off = 16; off > 0; off >>= 1) s += __shfl_xor_sync(0xffffffffu, s, off);
    if (lane == 0) ws[warp] = s;
    __syncthreads();
    float tot = 0.f;
#pragma unroll
    for (int w = 0; w < 8; w++) tot += ws[w];
    const float mean = tot * (1.0f / DD);
    __syncthreads();

    float vs = 0.f;
#pragma unroll
    for (int t = 0; t < 3; t++) { float d = xr[t] - mean; vs += d * d; }
#pragma unroll
    for (int off = 16; off > 0; off >>= 1) vs += __shfl_xor_sync(0xffffffffu, vs, off);
    if (lane == 0) ws[warp] = vs;
    __syncthreads();
    float vtot = 0.f;
#pragma unroll
    for (int w = 0; w < 8; w++) vtot += ws[w];
    const float rstd = rsqrtf(vtot * (1.0f / DD) + 1e-5f);

#pragma unroll
    for (int t = 0; t < 3; t++) {
        int i = tid + t * 256;
        o[i] = (xr[t] - mean) * rstd * g[i] + b[i];
    }
}

// ---------------- Flash attention: block = (b, h, 64-query tile) ----------------
#define FPAD 68
#define FA_SMEM (3 * 64 * FPAD * sizeof(float))

__global__ void __launch_bounds__(256)
fattn_k(const float* __restrict__ q, const float* __restrict__ k,
        const float* __restrict__ v, float* __restrict__ out) {
    extern __shared__ float sm[];
    float* Qt = sm;                  // [64][FPAD]  d-major
    float* Kt = sm + 64 * FPAD;      // [64][FPAD]  d-major; reused as Pt[k][q]
    float* Vs = sm + 2 * 64 * FPAD;  // [64][FPAD]  k-major

    const int tid = threadIdx.x;
    const int ty  = tid >> 4;
    const int tx  = tid & 15;
    const int qt0 = blockIdx.x * 64;
    const int h   = blockIdx.y;
    const int b   = blockIdx.z;
    const size_t base = ((size_t)b * NTOK) * DD + (size_t)h * HDIM;

#pragma unroll
    for (int it = 0; it < 4; it++) {
        int l = tid + it * 256;
        int row = l >> 4;
        int d4  = (l & 15) << 2;
        float4 val = *reinterpret_cast<const float4*>(&q[base + (size_t)(qt0 + row) * DD + d4]);
        Qt[(d4 + 0) * FPAD + row] = val.x;
        Qt[(d4 + 1) * FPAD + row] = val.y;
        Qt[(d4 + 2) * FPAD + row] = val.z;
        Qt[(d4 + 3) * FPAD + row] = val.w;
    }

    float O[4][4];
    float m_run[4], l_run[4];
#pragma unroll
    for (int i = 0; i < 4; i++) {
        m_run[i] = -1e30f; l_run[i] = 0.f;
#pragma unroll
        for (int j = 0; j < 4; j++) O[i][j] = 0.f;
    }
    __syncthreads();

    for (int kt0 = 0; kt0 < NTOK; kt0 += 64) {
#pragma unroll
        for (int it = 0; it < 4; it++) {
            int l = tid + it * 256;
            int row = l >> 4;
            int d4  = (l & 15) << 2;
            const size_t goff = base + (size_t)(kt0 + row) * DD + d4;
            float4 kv = *reinterpret_cast<const float4*>(&k[goff]);
            Kt[(d4 + 0) * FPAD + row] = kv.x;
            Kt[(d4 + 1) * FPAD + row] = kv.y;
            Kt[(d4 + 2) * FPAD + row] = kv.z;
            Kt[(d4 + 3) * FPAD + row] = kv.w;
            float4 vv = *reinterpret_cast<const float4*>(&v[goff]);
            *reinterpret_cast<float4*>(&Vs[row * FPAD + d4]) = vv;
        }
        __syncthreads();

        float S[4][4];
#pragma unroll
        for (int i = 0; i < 4; i++)
#pragma unroll
            for (int j = 0; j < 4; j++) S[i][j] = 0.f;

#pragma unroll 8
        for (int d = 0; d < HDIM; d++) {
            float4 a  = *reinterpret_cast<const float4*>(&Qt[d * FPAD + ty * 4]);
            float4 bq = *reinterpret_cast<const float4*>(&Kt[d * FPAD + tx * 4]);
            const float av[4] = {a.x, a.y, a.z, a.w};
            const float bv[4] = {bq.x, bq.y, bq.z, bq.w};
#pragma unroll
            for (int i = 0; i < 4; i++)
#pragma unroll
                for (int j = 0; j < 4; j++) S[i][j] = fmaf(av[i], bv[j], S[i][j]);
        }
        __syncthreads();

#pragma unroll
        for (int i = 0; i < 4; i++)
#pragma unroll
            for (int j = 0; j < 4; j++) {
                S[i][j] *= 0.125f;
                if (kt0 + tx * 4 + j >= NTOK) S[i][j] = -1e30f;
            }

#pragma unroll
        for (int i = 0; i < 4; i++) {
            float tm = fmaxf(fmaxf(S[i][0], S[i][1]), fmaxf(S[i][2], S[i][3]));
#pragma unroll
            for (int off = 8; off > 0; off >>= 1)
                tm = fmaxf(tm, __shfl_xor_sync(0xffffffffu, tm, off));
            float mn = fmaxf(m_run[i], tm);
            float alpha = expf(m_run[i] - mn);
            float ls = 0.f;
#pragma unroll
            for (int j = 0; j < 4; j++) {
                float p = expf(S[i][j] - mn);
                S[i][j] = p;
                ls += p;
            }
#pragma unroll
            for (int off = 8; off > 0; off >>= 1)
                ls += __shfl_xor_sync(0xffffffffu, ls, off);
            l_run[i] = l_run[i] * alpha + ls;
            m_run[i] = mn;
#pragma unroll
            for (int j = 0; j < 4; j++) O[i][j] *= alpha;
        }

#pragma unroll
        for (int j = 0; j < 4; j++)
#pragma unroll
            for (int i = 0; i < 4; i++)
                Kt[(tx * 4 + j) * FPAD + ty * 4 + i] = S[i][j];
        __syncthreads();

#pragma unroll 8
        for (int kk = 0; kk < 64; kk++) {
            float4 p  = *reinterpret_cast<const float4*>(&Kt[kk * FPAD + ty * 4]);
            float4 vv = *reinterpret_cast<const float4*>(&Vs[kk * FPAD + tx * 4]);
            const float pv[4] = {p.x, p.y, p.z, p.w};
            const float vvv[4] = {vv.x, vv.y, vv.z, vv.w};
#pragma unroll
            for (int i = 0; i < 4; i++)
#pragma unroll
                for (int j = 0; j < 4; j++) O[i][j] = fmaf(pv[i], vvv[j], O[i][j]);
        }
        __syncthreads();
    }

#pragma unroll
    for (int i = 0; i < 4; i++) {
        int qg = qt0 + ty * 4 + i;
        if (qg >= NTOK) continue;
        float inv = 1.0f / l_run[i];
        float4 o4 = make_float4(O[i][0] * inv, O[i][1] * inv, O[i][2] * inv, O[i][3] * inv);
        *reinterpret_cast<float4*>(&out[base + (size_t)qg * DD + tx * 4]) = o4;
    }
}

// ---------------- Head ----------------
__global__ void head_k(const float* __restrict__ cls, const float* __restrict__ hw,
                       const float* __restrict__ hb, float* __restrict__ out) {
    int idx = blockIdx.x * 256 + threadIdx.x;
    if (idx >= BB * NCLS) return;
    int b = idx / NCLS, c = idx % NCLS;
    const float* xr = &cls[b * DD];
    float acc = hb[c];
    for (int kk = 0; kk < DD; kk++) acc = fmaf(xr[kk], hw[kk * NCLS + c], acc);
    out[idx] = acc;
}

// ---------------- Launch ----------------
extern "C" void kernel_launch(void* const* d_in, const int* in_sizes, int n_in,
                              void* d_out, int out_size) {
    const float* x       = (const float*)d_in[0];
    const float* proj_w  = (const float*)d_in[1];
    const float* proj_b  = (const float*)d_in[2];
    const float* cls_emb = (const float*)d_in[3];
    const float* pos_emb = (const float*)d_in[4];
    const float* ln1_g   = (const float*)d_in[5];
    const float* ln1_b   = (const float*)d_in[6];
    const float* qw      = (const float*)d_in[7];
    const float* qb      = (const float*)d_in[8];
    const float* kw      = (const float*)d_in[9];
    const float* kb      = (const float*)d_in[10];
    const float* vw      = (const float*)d_in[11];
    const float* vb      = (const float*)d_in[12];
    const float* ow      = (const float*)d_in[13];
    const float* ob      = (const float*)d_in[14];
    const float* ln2_g   = (const float*)d_in[15];
    const float* ln2_b   = (const float*)d_in[16];
    const float* fcw     = (const float*)d_in[17];
    const float* fcb     = (const float*)d_in[18];
    const float* pw      = (const float*)d_in[19];
    const float* pb      = (const float*)d_in[20];
    const float* lnf_g   = (const float*)d_in[21];
    const float* lnf_b   = (const float*)d_in[22];
    const float* head_w  = (const float*)d_in[23];
    const float* head_b  = (const float*)d_in[24];
    float* out = (float*)d_out;
    (void)in_sizes; (void)n_in; (void)out_size;

    float *bt, *bemb, *bh, *by, *bq, *bk, *bv, *bao, *bmlp, *bcls;
    cudaGetSymbolAddress((void**)&bt,   g_t);
    cudaGetSymbolAddress((void**)&bemb, g_emb);
    cudaGetSymbolAddress((void**)&bh,   g_h);
    cudaGetSymbolAddress((void**)&by,   g_y);
    cudaGetSymbolAddress((void**)&bq,   g_q);
    cudaGetSymbolAddress((void**)&bk,   g_k);
    cudaGetSymbolAddress((void**)&bv,   g_v);
    cudaGetSymbolAddress((void**)&bao,  g_ao);
    cudaGetSymbolAddress((void**)&bmlp, g_mlp);
    cudaGetSymbolAddress((void**)&bcls, g_cls);

    cudaFuncSetAttribute(fattn_k, cudaFuncAttributeMaxDynamicSharedMemorySize, (int)FA_SMEM);

    // Patch embed
    patch_k<<<(MPATCH*DD + 255)/256, 256>>>(x, bt);
    gemm_tf32_k<<<dim3(DD/128, MPATCH/128), 256>>>(bt, proj_w, proj_b, bemb, MPATCH, DD, DD, 0);
    assemble_k<<<(BB*NTOK*DD + 255)/256, 256>>>(bemb, cls_emb, pos_emb, bh);

    const int MB = MPAD / 128;  // 37
    const int QTILES = (NTOK + 63) / 64;  // 10
    for (int l = 0; l < LL; l++) {
        const size_t wo  = (size_t)l * DD * DD;
        const size_t wfc = (size_t)l * DD * MLPD;

        ln_k<<<MTOK, 256>>>(bh, by, ln1_g + l*DD, ln1_b + l*DD, DD);
        gemm_tf32_k<<<dim3(DD/128, MB), 256>>>(by, qw + wo, qb + l*DD, bq, MPAD, DD, DD, 0);
        gemm_tf32_k<<<dim3(DD/128, MB), 256>>>(by, kw + wo, kb + l*DD, bk, MPAD, DD, DD, 0);
        gemm_tf32_k<<<dim3(DD/128, MB), 256>>>(by, vw + wo, vb + l*DD, bv, MPAD, DD, DD, 0);
        fattn_k<<<dim3(QTILES, NHH, BB), 256, FA_SMEM>>>(bq, bk, bv, bao);
        gemm_tf32_k<<<dim3(DD/128, MB), 256>>>(bao, ow + wo, ob + l*DD, bh, MPAD, DD, DD, 1);

        ln_k<<<MTOK, 256>>>(bh, by, ln2_g + l*DD, ln2_b + l*DD, DD);
        gemm_tf32_k<<<dim3(MLPD/128, MB), 256>>>(by, fcw + wfc, fcb + l*MLPD, bmlp, MPAD, MLPD, DD, 2);
        gemm_tf32_k<<<dim3(DD/128, MB), 256>>>(bmlp, pw + wfc, pb + l*DD, bh, MPAD, DD, MLPD, 1);
    }

    ln_k<<<BB, 256>>>(bh, bcls, lnf_g, lnf_b, (long)NTOK * DD);
    head_k<<<(BB*NCLS + 255)/256, 256>>>(bcls, head_w, head_b, out);
}

// round 14
// speedup vs baseline: 1.2971x; 1.2971x over previous
#include <cuda_runtime.h>
#include <cuda_fp16.h>
#include <math.h>
#include <stdint.h>

// ---------------- Config ----------------
#define BB     8
#define CC     3
#define HH     384
#define WW     384
#define PP     16
#define DD     768
#define NHH    12
#define MLPD   3072
#define LL     12
#define NCLS   1000
#define NPAT   576
#define NTOK   577
#define HDIM   64
#define MTOK   (BB*NTOK)    // 4616
#define MPAD   4736         // 37*128
#define MPATCH (BB*NPAT)    // 4608 = 36*128

// ---------------- Scratch (device globals; .bss zero-init) ----------------
__device__ float g_t  [MPATCH*DD];
__device__ float g_emb[MPATCH*DD];
__device__ float g_h  [MPAD*DD];
__device__ float g_y  [MPAD*DD];
__device__ float g_q  [MPAD*DD];
__device__ float g_k  [MPAD*DD];
__device__ float g_v  [MPAD*DD];
__device__ float g_ao [MPAD*DD];
__device__ float g_mlp[MPAD*MLPD];
__device__ float g_cls[BB*DD];

// ---------------- Patch gather (faithful batch-mixing flatten) ----------------
__global__ void patch_k(const float* __restrict__ x, float* __restrict__ t) {
    int idx = blockIdx.x * 256 + threadIdx.x;
    if (idx >= MPATCH * DD) return;
    int p1  = idx / 221184;          // B*C*GH*GW*P
    int rem = idx % 221184;
    int b   = rem / 27648;  rem %= 27648;
    int c   = rem / 9216;   rem %= 9216;
    int gh  = rem / 384;    rem %= 384;
    int gw  = rem / 16;
    int p2  = rem % 16;
    t[idx] = x[(((b*CC + c)*HH) + gh*PP + p1) * WW + gw*PP + p2];
}

// ---------------- Assemble: CLS + pos_emb ----------------
__global__ void assemble_k(const float* __restrict__ emb, const float* __restrict__ cls_emb,
                           const float* __restrict__ pos, float* __restrict__ h) {
    int idx = blockIdx.x * 256 + threadIdx.x;
    if (idx >= BB * NTOK * DD) return;
    int d = idx % DD;
    int n = (idx / DD) % NTOK;
    int b = idx / (DD * NTOK);
    float val = (n == 0) ? cls_emb[d] : emb[((size_t)b*NPAT + (n-1))*DD + d];
    h[idx] = val + pos[n*DD + d];
}

// ---------------- FP16 tensor-core GEMM (m16n8k16, fp32 accumulate) ----------------
// Layout: As half2[row][k2], stride APAD2=12 (fragment loads hit all 32 banks).
//         Bs half2[k2][n],  stride BPAD2=136.
#define APAD2 12
#define BPAD2 136

__device__ __forceinline__ unsigned packh2(float lo, float hi) {
    __half2 h = __floats2half2_rn(lo, hi);
    return *reinterpret_cast<unsigned*>(&h);
}

__device__ __forceinline__ void mma_f16(float* d, const unsigned* a, const unsigned* b) {
    asm volatile(
        "mma.sync.aligned.m16n8k16.row.col.f32.f16.f16.f32 "
        "{%0,%1,%2,%3}, {%4,%5,%6,%7}, {%8,%9}, {%0,%1,%2,%3};"
        : "+f"(d[0]), "+f"(d[1]), "+f"(d[2]), "+f"(d[3])
        : "r"(a[0]), "r"(a[1]), "r"(a[2]), "r"(a[3]), "r"(b[0]), "r"(b[1]));
}

__global__ void __launch_bounds__(256, 2)
gemm_f16_k(const float* __restrict__ A, const float* __restrict__ W,
           const float* __restrict__ bias, float* __restrict__ C,
           int M, int N, int K, int mode) {
    __shared__ unsigned As[2][128 * APAD2];  // 2 x 6KB
    __shared__ unsigned Bs[2][8 * BPAD2];    // 2 x 4.25KB

    const int tid  = threadIdx.x;
    const int lane = tid & 31;
    const int warp = tid >> 5;
    const int wm   = warp & 1;
    const int wn   = warp >> 1;
    const int gid  = lane >> 2;
    const int tig  = lane & 3;
    const int row0 = blockIdx.y * 128;
    const int col0 = blockIdx.x * 128;

    // A loader: rows ar2, ar2+64; one float4 of k each (kq..kq+3)
    const int ar2 = tid >> 2;            // 0..63
    const int kq  = (tid & 3) << 2;      // 0,4,8,12
    const int kh  = kq >> 1;             // half2 index 0,2,4,6
    // B loader: k-pair rows 2*bk2, 2*bk2+1; 4 n values
    const int bk2 = tid >> 5;            // 0..7
    const int bn4 = (tid & 31) << 2;     // 0..124

    float acc[4][4][4];
#pragma unroll
    for (int i = 0; i < 4; i++)
#pragma unroll
        for (int j = 0; j < 4; j++)
#pragma unroll
            for (int c = 0; c < 4; c++) acc[i][j][c] = 0.f;

    // preload k-tile 0 into buffer 0
    {
        float4 a0 = *reinterpret_cast<const float4*>(&A[(size_t)(row0 + ar2) * K + kq]);
        float4 a1 = *reinterpret_cast<const float4*>(&A[(size_t)(row0 + ar2 + 64) * K + kq]);
        *reinterpret_cast<uint2*>(&As[0][ar2 * APAD2 + kh]) =
            make_uint2(packh2(a0.x, a0.y), packh2(a0.z, a0.w));
        *reinterpret_cast<uint2*>(&As[0][(ar2 + 64) * APAD2 + kh]) =
            make_uint2(packh2(a1.x, a1.y), packh2(a1.z, a1.w));
        float4 b0 = *reinterpret_cast<const float4*>(&W[(size_t)(2 * bk2) * N + col0 + bn4]);
        float4 b1 = *reinterpret_cast<const float4*>(&W[(size_t)(2 * bk2 + 1) * N + col0 + bn4]);
        *reinterpret_cast<uint4*>(&Bs[0][bk2 * BPAD2 + bn4]) =
            make_uint4(packh2(b0.x, b1.x), packh2(b0.y, b1.y),
                       packh2(b0.z, b1.z), packh2(b0.w, b1.w));
    }
    __syncthreads();

    int cur = 0;
    for (int k0 = 0; k0 < K; k0 += 16) {
        const bool has_next = (k0 + 16) < K;
        float4 pa0, pa1, pb0, pb1;
        if (has_next) {
            const int kn = k0 + 16;
            pa0 = *reinterpret_cast<const float4*>(&A[(size_t)(row0 + ar2) * K + kn + kq]);
            pa1 = *reinterpret_cast<const float4*>(&A[(size_t)(row0 + ar2 + 64) * K + kn + kq]);
            pb0 = *reinterpret_cast<const float4*>(&W[(size_t)(kn + 2 * bk2) * N + col0 + bn4]);
            pb1 = *reinterpret_cast<const float4*>(&W[(size_t)(kn + 2 * bk2 + 1) * N + col0 + bn4]);
        }

        // compute on current buffer: one m16n8k16 step covers the whole BK=16
        const unsigned* Asc = As[cur];
        const unsigned* Bsc = Bs[cur];
        unsigned af[4][4], bf[4][2];
#pragma unroll
        for (int mt = 0; mt < 4; mt++) {
            int r = wm * 64 + mt * 16 + gid;
            af[mt][0] = Asc[(r    ) * APAD2 + tig    ];
            af[mt][1] = Asc[(r + 8) * APAD2 + tig    ];
            af[mt][2] = Asc[(r    ) * APAD2 + tig + 4];
            af[mt][3] = Asc[(r + 8) * APAD2 + tig + 4];
        }
#pragma unroll
        for (int nt = 0; nt < 4; nt++) {
            int n = wn * 32 + nt * 8 + gid;
            bf[nt][0] = Bsc[(tig    ) * BPAD2 + n];
            bf[nt][1] = Bsc[(tig + 4) * BPAD2 + n];
        }
#pragma unroll
        for (int mt = 0; mt < 4; mt++)
#pragma unroll
            for (int nt = 0; nt < 4; nt++)
                mma_f16(acc[mt][nt], af[mt], bf[nt]);

        if (has_next) {
            const int nxt = cur ^ 1;
            *reinterpret_cast<uint2*>(&As[nxt][ar2 * APAD2 + kh]) =
                make_uint2(packh2(pa0.x, pa0.y), packh2(pa0.z, pa0.w));
            *reinterpret_cast<uint2*>(&As[nxt][(ar2 + 64) * APAD2 + kh]) =
                make_uint2(packh2(pa1.x, pa1.y), packh2(pa1.z, pa1.w));
            *reinterpret_cast<uint4*>(&Bs[nxt][bk2 * BPAD2 + bn4]) =
                make_uint4(packh2(pb0.x, pb1.x), packh2(pb0.y, pb1.y),
                           packh2(pb0.z, pb1.z), packh2(pb0.w, pb1.w));
            __syncthreads();
            cur = nxt;
        }
    }

    // epilogue (same D mapping as m16n8k8: rows gid/gid+8, cols tig*2, tig*2+1)
#pragma unroll
    for (int mt = 0; mt < 4; mt++) {
#pragma unroll
        for (int nt = 0; nt < 4; nt++) {
#pragma unroll
            for (int c = 0; c < 4; c++) {
                int r   = row0 + wm * 64 + mt * 16 + gid + ((c >> 1) << 3);
                int col = col0 + wn * 32 + nt * 8 + tig * 2 + (c & 1);
                if (r >= M) continue;
                float v = acc[mt][nt][c] + bias[col];
                if (mode == 1)      v += C[(size_t)r * N + col];
                else if (mode == 2) v = 0.5f * v * (1.0f + erff(v * 0.70710678118654752f));
                C[(size_t)r * N + col] = v;
            }
        }
    }
}

// ---------------- LayerNorm (shuffle reductions) ----------------
__global__ void ln_k(const float* __restrict__ in, float* __restrict__ out,
                     const float* __restrict__ g, const float* __restrict__ b,
                     long in_stride) {
    const int row = blockIdx.x;
    const float* x = in + (size_t)row * in_stride;
    float* o = out + (size_t)row * DD;
    __shared__ float ws[8];
    const int tid  = threadIdx.x;
    const int lane = tid & 31;
    const int warp = tid >> 5;

    float xr[3];
    float s = 0.f;
#pragma unroll
    for (int t = 0; t < 3; t++) { xr[t] = x[tid + t * 256]; s += xr[t]; }
#pragma unroll
    for (int off = 16; off > 0; off >>= 1) s += __shfl_xor_sync(0xffffffffu, s, off);
    if (lane == 0) ws[warp] = s;
    __syncthreads();
    float tot = 0.f;
#pragma unroll
    for (int w = 0; w < 8; w++) tot += ws[w];
    const float mean = tot * (1.0f / DD);
    __syncthreads();

    float vs = 0.f;
#pragma unroll
    for (int t = 0; t < 3; t++) { float d = xr[t] - mean; vs += d * d; }
#pragma unroll
    for (int off = 16; off > 0; off >>= 1) vs += __shfl_xor_sync(0xffffffffu, vs, off);
    if (lane == 0) ws[warp] = vs;
    __syncthreads();
    float vtot = 0.f;
#pragma unroll
    for (int w = 0; w < 8; w++) vtot += ws[w];
    const float rstd = rsqrtf(vtot * (1.0f / DD) + 1e-5f);

#pragma unroll
    for (int t = 0; t < 3; t++) {
        int i = tid + t * 256;
        o[i] = (xr[t] - mean) * rstd * g[i] + b[i];
    }
}

// ---------------- Flash attention: block = (b, h, 64-query tile) ----------------
#define FPAD 68
#define FA_SMEM (3 * 64 * FPAD * sizeof(float))

__global__ void __launch_bounds__(256)
fattn_k(const float* __restrict__ q, const float* __restrict__ k,
        const float* __restrict__ v, float* __restrict__ out) {
    extern __shared__ float sm[];
    float* Qt = sm;                  // [64][FPAD]  d-major
    float* Kt = sm + 64 * FPAD;      // [64][FPAD]  d-major; reused as Pt[k][q]
    float* Vs = sm + 2 * 64 * FPAD;  // [64][FPAD]  k-major

    const int tid = threadIdx.x;
    const int ty  = tid >> 4;
    const int tx  = tid & 15;
    const int qt0 = blockIdx.x * 64;
    const int h   = blockIdx.y;
    const int b   = blockIdx.z;
    const size_t base = ((size_t)b * NTOK) * DD + (size_t)h * HDIM;

#pragma unroll
    for (int it = 0; it < 4; it++) {
        int l = tid + it * 256;
        int row = l >> 4;
        int d4  = (l & 15) << 2;
        float4 val = *reinterpret_cast<const float4*>(&q[base + (size_t)(qt0 + row) * DD + d4]);
        Qt[(d4 + 0) * FPAD + row] = val.x;
        Qt[(d4 + 1) * FPAD + row] = val.y;
        Qt[(d4 + 2) * FPAD + row] = val.z;
        Qt[(d4 + 3) * FPAD + row] = val.w;
    }

    float O[4][4];
    float m_run[4], l_run[4];
#pragma unroll
    for (int i = 0; i < 4; i++) {
        m_run[i] = -1e30f; l_run[i] = 0.f;
#pragma unroll
        for (int j = 0; j < 4; j++) O[i][j] = 0.f;
    }
    __syncthreads();

    for (int kt0 = 0; kt0 < NTOK; kt0 += 64) {
#pragma unroll
        for (int it = 0; it < 4; it++) {
            int l = tid + it * 256;
            int row = l >> 4;
            int d4  = (l & 15) << 2;
            const size_t goff = base + (size_t)(kt0 + row) * DD + d4;
            float4 kv = *reinterpret_cast<const float4*>(&k[goff]);
            Kt[(d4 + 0) * FPAD + row] = kv.x;
            Kt[(d4 + 1) * FPAD + row] = kv.y;
            Kt[(d4 + 2) * FPAD + row] = kv.z;
            Kt[(d4 + 3) * FPAD + row] = kv.w;
            float4 vv = *reinterpret_cast<const float4*>(&v[goff]);
            *reinterpret_cast<float4*>(&Vs[row * FPAD + d4]) = vv;
        }
        __syncthreads();

        float S[4][4];
#pragma unroll
        for (int i = 0; i < 4; i++)
#pragma unroll
            for (int j = 0; j < 4; j++) S[i][j] = 0.f;

#pragma unroll 8
        for (int d = 0; d < HDIM; d++) {
            float4 a  = *reinterpret_cast<const float4*>(&Qt[d * FPAD + ty * 4]);
            float4 bq = *reinterpret_cast<const float4*>(&Kt[d * FPAD + tx * 4]);
            const float av[4] = {a.x, a.y, a.z, a.w};
            const float bv[4] = {bq.x, bq.y, bq.z, bq.w};
#pragma unroll
            for (int i = 0; i < 4; i++)
#pragma unroll
                for (int j = 0; j < 4; j++) S[i][j] = fmaf(av[i], bv[j], S[i][j]);
        }
        __syncthreads();

#pragma unroll
        for (int i = 0; i < 4; i++)
#pragma unroll
            for (int j = 0; j < 4; j++) {
                S[i][j] *= 0.125f;
                if (kt0 + tx * 4 + j >= NTOK) S[i][j] = -1e30f;
            }

#pragma unroll
        for (int i = 0; i < 4; i++) {
            float tm = fmaxf(fmaxf(S[i][0], S[i][1]), fmaxf(S[i][2], S[i][3]));
#pragma unroll
            for (int off = 8; off > 0; off >>= 1)
                tm = fmaxf(tm, __shfl_xor_sync(0xffffffffu, tm, off));
            float mn = fmaxf(m_run[i], tm);
            float alpha = expf(m_run[i] - mn);
            float ls = 0.f;
#pragma unroll
            for (int j = 0; j < 4; j++) {
                float p = expf(S[i][j] - mn);
                S[i][j] = p;
                ls += p;
            }
#pragma unroll
            for (int off = 8; off > 0; off >>= 1)
                ls += __shfl_xor_sync(0xffffffffu, ls, off);
            l_run[i] = l_run[i] * alpha + ls;
            m_run[i] = mn;
#pragma unroll
            for (int j = 0; j < 4; j++) O[i][j] *= alpha;
        }

#pragma unroll
        for (int j = 0; j < 4; j++)
#pragma unroll
            for (int i = 0; i < 4; i++)
                Kt[(tx * 4 + j) * FPAD + ty * 4 + i] = S[i][j];
        __syncthreads();

#pragma unroll 8
        for (int kk = 0; kk < 64; kk++) {
            float4 p  = *reinterpret_cast<const float4*>(&Kt[kk * FPAD + ty * 4]);
            float4 vv = *reinterpret_cast<const float4*>(&Vs[kk * FPAD + tx * 4]);
            const float pv[4] = {p.x, p.y, p.z, p.w};
            const float vvv[4] = {vv.x, vv.y, vv.z, vv.w};
#pragma unroll
            for (int i = 0; i < 4; i++)
#pragma unroll
                for (int j = 0; j < 4; j++) O[i][j] = fmaf(pv[i], vvv[j], O[i][j]);
        }
        __syncthreads();
    }

#pragma unroll
    for (int i = 0; i < 4; i++) {
        int qg = qt0 + ty * 4 + i;
        if (qg >= NTOK) continue;
        float inv = 1.0f / l_run[i];
        float4 o4 = make_float4(O[i][0] * inv, O[i][1] * inv, O[i][2] * inv, O[i][3] * inv);
        *reinterpret_cast<float4*>(&out[base + (size_t)qg * DD + tx * 4]) = o4;
    }
}

// ---------------- Head ----------------
__global__ void head_k(const float* __restrict__ cls, const float* __restrict__ hw,
                       const float* __restrict__ hb, float* __restrict__ out) {
    int idx = blockIdx.x * 256 + threadIdx.x;
    if (idx >= BB * NCLS) return;
    int b = idx / NCLS, c = idx % NCLS;
    const float* xr = &cls[b * DD];
    float acc = hb[c];
    for (int kk = 0; kk < DD; kk++) acc = fmaf(xr[kk], hw[kk * NCLS + c], acc);
    out[idx] = acc;
}

// ---------------- Launch ----------------
extern "C" void kernel_launch(void* const* d_in, const int* in_sizes, int n_in,
                              void* d_out, int out_size) {
    const float* x       = (const float*)d_in[0];
    const float* proj_w  = (const float*)d_in[1];
    const float* proj_b  = (const float*)d_in[2];
    const float* cls_emb = (const float*)d_in[3];
    const float* pos_emb = (const float*)d_in[4];
    const float* ln1_g   = (const float*)d_in[5];
    const float* ln1_b   = (const float*)d_in[6];
    const float* qw      = (const float*)d_in[7];
    const float* qb      = (const float*)d_in[8];
    const float* kw      = (const float*)d_in[9];
    const float* kb      = (const float*)d_in[10];
    const float* vw      = (const float*)d_in[11];
    const float* vb      = (const float*)d_in[12];
    const float* ow      = (const float*)d_in[13];
    const float* ob      = (const float*)d_in[14];
    const float* ln2_g   = (const float*)d_in[15];
    const float* ln2_b   = (const float*)d_in[16];
    const float* fcw     = (const float*)d_in[17];
    const float* fcb     = (const float*)d_in[18];
    const float* pw      = (const float*)d_in[19];
    const float* pb      = (const float*)d_in[20];
    const float* lnf_g   = (const float*)d_in[21];
    const float* lnf_b   = (const float*)d_in[22];
    const float* head_w  = (const float*)d_in[23];
    const float* head_b  = (const float*)d_in[24];
    float* out = (float*)d_out;
    (void)in_sizes; (void)n_in; (void)out_size;

    float *bt, *bemb, *bh, *by, *bq, *bk, *bv, *bao, *bmlp, *bcls;
    cudaGetSymbolAddress((void**)&bt,   g_t);
    cudaGetSymbolAddress((void**)&bemb, g_emb);
    cudaGetSymbolAddress((void**)&bh,   g_h);
    cudaGetSymbolAddress((void**)&by,   g_y);
    cudaGetSymbolAddress((void**)&bq,   g_q);
    cudaGetSymbolAddress((void**)&bk,   g_k);
    cudaGetSymbolAddress((void**)&bv,   g_v);
    cudaGetSymbolAddress((void**)&bao,  g_ao);
    cudaGetSymbolAddress((void**)&bmlp, g_mlp);
    cudaGetSymbolAddress((void**)&bcls, g_cls);

    cudaFuncSetAttribute(fattn_k, cudaFuncAttributeMaxDynamicSharedMemorySize, (int)FA_SMEM);

    // Patch embed
    patch_k<<<(MPATCH*DD + 255)/256, 256>>>(x, bt);
    gemm_f16_k<<<dim3(DD/128, MPATCH/128), 256>>>(bt, proj_w, proj_b, bemb, MPATCH, DD, DD, 0);
    assemble_k<<<(BB*NTOK*DD + 255)/256, 256>>>(bemb, cls_emb, pos_emb, bh);

    const int MB = MPAD / 128;  // 37
    const int QTILES = (NTOK + 63) / 64;  // 10
    for (int l = 0; l < LL; l++) {
        const size_t wo  = (size_t)l * DD * DD;
        const size_t wfc = (size_t)l * DD * MLPD;

        ln_k<<<MTOK, 256>>>(bh, by, ln1_g + l*DD, ln1_b + l*DD, DD);
        gemm_f16_k<<<dim3(DD/128, MB), 256>>>(by, qw + wo, qb + l*DD, bq, MPAD, DD, DD, 0);
        gemm_f16_k<<<dim3(DD/128, MB), 256>>>(by, kw + wo, kb + l*DD, bk, MPAD, DD, DD, 0);
        gemm_f16_k<<<dim3(DD/128, MB), 256>>>(by, vw + wo, vb + l*DD, bv, MPAD, DD, DD, 0);
        fattn_k<<<dim3(QTILES, NHH, BB), 256, FA_SMEM>>>(bq, bk, bv, bao);
        gemm_f16_k<<<dim3(DD/128, MB), 256>>>(bao, ow + wo, ob + l*DD, bh, MPAD, DD, DD, 1);

        ln_k<<<MTOK, 256>>>(bh, by, ln2_g + l*DD, ln2_b + l*DD, DD);
        gemm_f16_k<<<dim3(MLPD/128, MB), 256>>>(by, fcw + wfc, fcb + l*MLPD, bmlp, MPAD, MLPD, DD, 2);
        gemm_f16_k<<<dim3(DD/128, MB), 256>>>(bmlp, pw + wfc, pb + l*DD, bh, MPAD, DD, MLPD, 1);
    }

    ln_k<<<BB, 256>>>(bh, bcls, lnf_g, lnf_b, (long)NTOK * DD);
    head_k<<<(BB*NCLS + 255)/256, 256>>>(bcls, head_w, head_b, out);
}

// round 15
// speedup vs baseline: 1.8074x; 1.3934x over previous
#include <cuda_runtime.h>
#include <cuda_fp16.h>
#include <math.h>
#include <stdint.h>

// ---------------- Config ----------------
#define BB     8
#define CC     3
#define HH     384
#define WW     384
#define PP     16
#define DD     768
#define NHH    12
#define MLPD   3072
#define LL     12
#define NCLS   1000
#define NPAT   576
#define NTOK   577
#define HDIM   64
#define MTOK   (BB*NTOK)    // 4616
#define MPAD   4736         // 37*128
#define MPATCH (BB*NPAT)    // 4608 = 36*128

// ---------------- Scratch (device globals; .bss zero-init) ----------------
__device__ float g_t  [MPATCH*DD];
__device__ float g_emb[MPATCH*DD];
__device__ float g_h  [MPAD*DD];
__device__ float g_y  [MPAD*DD];
__device__ float g_q  [MPAD*DD];
__device__ float g_k  [MPAD*DD];
__device__ float g_v  [MPAD*DD];
__device__ float g_ao [MPAD*DD];
__device__ float g_mlp[MPAD*MLPD];
__device__ float g_cls[BB*DD];

// ---------------- Patch gather (faithful batch-mixing flatten) ----------------
__global__ void patch_k(const float* __restrict__ x, float* __restrict__ t) {
    int idx = blockIdx.x * 256 + threadIdx.x;
    if (idx >= MPATCH * DD) return;
    int p1  = idx / 221184;          // B*C*GH*GW*P
    int rem = idx % 221184;
    int b   = rem / 27648;  rem %= 27648;
    int c   = rem / 9216;   rem %= 9216;
    int gh  = rem / 384;    rem %= 384;
    int gw  = rem / 16;
    int p2  = rem % 16;
    t[idx] = x[(((b*CC + c)*HH) + gh*PP + p1) * WW + gw*PP + p2];
}

// ---------------- Assemble: CLS + pos_emb ----------------
__global__ void assemble_k(const float* __restrict__ emb, const float* __restrict__ cls_emb,
                           const float* __restrict__ pos, float* __restrict__ h) {
    int idx = blockIdx.x * 256 + threadIdx.x;
    if (idx >= BB * NTOK * DD) return;
    int d = idx % DD;
    int n = (idx / DD) % NTOK;
    int b = idx / (DD * NTOK);
    float val = (n == 0) ? cls_emb[d] : emb[((size_t)b*NPAT + (n-1))*DD + d];
    h[idx] = val + pos[n*DD + d];
}

// ---------------- FP16 tensor-core GEMM (m16n8k16, fp32 accumulate) ----------------
#define APAD2 12
#define BPAD2 136

__device__ __forceinline__ unsigned packh2(float lo, float hi) {
    __half2 h = __floats2half2_rn(lo, hi);
    return *reinterpret_cast<unsigned*>(&h);
}

__device__ __forceinline__ void mma_f16(float* d, const unsigned* a, const unsigned* b) {
    asm volatile(
        "mma.sync.aligned.m16n8k16.row.col.f32.f16.f16.f32 "
        "{%0,%1,%2,%3}, {%4,%5,%6,%7}, {%8,%9}, {%0,%1,%2,%3};"
        : "+f"(d[0]), "+f"(d[1]), "+f"(d[2]), "+f"(d[3])
        : "r"(a[0]), "r"(a[1]), "r"(a[2]), "r"(a[3]), "r"(b[0]), "r"(b[1]));
}

__device__ __forceinline__ void gemm_f16_body(
        const float* __restrict__ A, const float* __restrict__ W,
        const float* __restrict__ bias, float* __restrict__ C,
        int M, int N, int K, int mode, int bx, int by) {
    __shared__ unsigned As[2][128 * APAD2];
    __shared__ unsigned Bs[2][8 * BPAD2];

    const int tid  = threadIdx.x;
    const int lane = tid & 31;
    const int warp = tid >> 5;
    const int wm   = warp & 1;
    const int wn   = warp >> 1;
    const int gid  = lane >> 2;
    const int tig  = lane & 3;
    const int row0 = by * 128;
    const int col0 = bx * 128;

    const int ar2 = tid >> 2;
    const int kq  = (tid & 3) << 2;
    const int kh  = kq >> 1;
    const int bk2 = tid >> 5;
    const int bn4 = (tid & 31) << 2;

    float acc[4][4][4];
#pragma unroll
    for (int i = 0; i < 4; i++)
#pragma unroll
        for (int j = 0; j < 4; j++)
#pragma unroll
            for (int c = 0; c < 4; c++) acc[i][j][c] = 0.f;

    {
        float4 a0 = *reinterpret_cast<const float4*>(&A[(size_t)(row0 + ar2) * K + kq]);
        float4 a1 = *reinterpret_cast<const float4*>(&A[(size_t)(row0 + ar2 + 64) * K + kq]);
        *reinterpret_cast<uint2*>(&As[0][ar2 * APAD2 + kh]) =
            make_uint2(packh2(a0.x, a0.y), packh2(a0.z, a0.w));
        *reinterpret_cast<uint2*>(&As[0][(ar2 + 64) * APAD2 + kh]) =
            make_uint2(packh2(a1.x, a1.y), packh2(a1.z, a1.w));
        float4 b0 = *reinterpret_cast<const float4*>(&W[(size_t)(2 * bk2) * N + col0 + bn4]);
        float4 b1 = *reinterpret_cast<const float4*>(&W[(size_t)(2 * bk2 + 1) * N + col0 + bn4]);
        *reinterpret_cast<uint4*>(&Bs[0][bk2 * BPAD2 + bn4]) =
            make_uint4(packh2(b0.x, b1.x), packh2(b0.y, b1.y),
                       packh2(b0.z, b1.z), packh2(b0.w, b1.w));
    }
    __syncthreads();

    int cur = 0;
    for (int k0 = 0; k0 < K; k0 += 16) {
        const bool has_next = (k0 + 16) < K;
        float4 pa0, pa1, pb0, pb1;
        if (has_next) {
            const int kn = k0 + 16;
            pa0 = *reinterpret_cast<const float4*>(&A[(size_t)(row0 + ar2) * K + kn + kq]);
            pa1 = *reinterpret_cast<const float4*>(&A[(size_t)(row0 + ar2 + 64) * K + kn + kq]);
            pb0 = *reinterpret_cast<const float4*>(&W[(size_t)(kn + 2 * bk2) * N + col0 + bn4]);
            pb1 = *reinterpret_cast<const float4*>(&W[(size_t)(kn + 2 * bk2 + 1) * N + col0 + bn4]);
        }

        const unsigned* Asc = As[cur];
        const unsigned* Bsc = Bs[cur];
        unsigned af[4][4], bf[4][2];
#pragma unroll
        for (int mt = 0; mt < 4; mt++) {
            int r = wm * 64 + mt * 16 + gid;
            af[mt][0] = Asc[(r    ) * APAD2 + tig    ];
            af[mt][1] = Asc[(r + 8) * APAD2 + tig    ];
            af[mt][2] = Asc[(r    ) * APAD2 + tig + 4];
            af[mt][3] = Asc[(r + 8) * APAD2 + tig + 4];
        }
#pragma unroll
        for (int nt = 0; nt < 4; nt++) {
            int n = wn * 32 + nt * 8 + gid;
            bf[nt][0] = Bsc[(tig    ) * BPAD2 + n];
            bf[nt][1] = Bsc[(tig + 4) * BPAD2 + n];
        }
#pragma unroll
        for (int mt = 0; mt < 4; mt++)
#pragma unroll
            for (int nt = 0; nt < 4; nt++)
                mma_f16(acc[mt][nt], af[mt], bf[nt]);

        if (has_next) {
            const int nxt = cur ^ 1;
            *reinterpret_cast<uint2*>(&As[nxt][ar2 * APAD2 + kh]) =
                make_uint2(packh2(pa0.x, pa0.y), packh2(pa0.z, pa0.w));
            *reinterpret_cast<uint2*>(&As[nxt][(ar2 + 64) * APAD2 + kh]) =
                make_uint2(packh2(pa1.x, pa1.y), packh2(pa1.z, pa1.w));
            *reinterpret_cast<uint4*>(&Bs[nxt][bk2 * BPAD2 + bn4]) =
                make_uint4(packh2(pb0.x, pb1.x), packh2(pb0.y, pb1.y),
                           packh2(pb0.z, pb1.z), packh2(pb0.w, pb1.w));
            __syncthreads();
            cur = nxt;
        }
    }

#pragma unroll
    for (int mt = 0; mt < 4; mt++) {
#pragma unroll
        for (int nt = 0; nt < 4; nt++) {
#pragma unroll
            for (int c = 0; c < 4; c++) {
                int r   = row0 + wm * 64 + mt * 16 + gid + ((c >> 1) << 3);
                int col = col0 + wn * 32 + nt * 8 + tig * 2 + (c & 1);
                if (r >= M) continue;
                float v = acc[mt][nt][c] + bias[col];
                if (mode == 1)      v += C[(size_t)r * N + col];
                else if (mode == 2) v = 0.5f * v * (1.0f + erff(v * 0.70710678118654752f));
                C[(size_t)r * N + col] = v;
            }
        }
    }
}

__global__ void __launch_bounds__(256, 2)
gemm_f16_k(const float* __restrict__ A, const float* __restrict__ W,
           const float* __restrict__ bias, float* __restrict__ C,
           int M, int N, int K, int mode) {
    gemm_f16_body(A, W, bias, C, M, N, K, mode, blockIdx.x, blockIdx.y);
}

// fused QKV projections: blockIdx.z selects weight/bias/output
__global__ void __launch_bounds__(256, 2)
gemm_f16_qkv_k(const float* __restrict__ A,
               const float* __restrict__ qw, const float* __restrict__ kw,
               const float* __restrict__ vw, const float* __restrict__ qb,
               const float* __restrict__ kb, const float* __restrict__ vb,
               float* __restrict__ oq, float* __restrict__ ok, float* __restrict__ ov,
               int M, int N, int K) {
    const float* W; const float* bias; float* C;
    if (blockIdx.z == 0)      { W = qw; bias = qb; C = oq; }
    else if (blockIdx.z == 1) { W = kw; bias = kb; C = ok; }
    else                      { W = vw; bias = vb; C = ov; }
    gemm_f16_body(A, W, bias, C, M, N, K, 0, blockIdx.x, blockIdx.y);
}

// ---------------- LayerNorm (shuffle reductions) ----------------
__global__ void ln_k(const float* __restrict__ in, float* __restrict__ out,
                     const float* __restrict__ g, const float* __restrict__ b,
                     long in_stride) {
    const int row = blockIdx.x;
    const float* x = in + (size_t)row * in_stride;
    float* o = out + (size_t)row * DD;
    __shared__ float ws[8];
    const int tid  = threadIdx.x;
    const int lane = tid & 31;
    const int warp = tid >> 5;

    float xr[3];
    float s = 0.f;
#pragma unroll
    for (int t = 0; t < 3; t++) { xr[t] = x[tid + t * 256]; s += xr[t]; }
#pragma unroll
    for (int off = 16; off > 0; off >>= 1) s += __shfl_xor_sync(0xffffffffu, s, off);
    if (lane == 0) ws[warp] = s;
    __syncthreads();
    float tot = 0.f;
#pragma unroll
    for (int w = 0; w < 8; w++) tot += ws[w];
    const float mean = tot * (1.0f / DD);
    __syncthreads();

    float vs = 0.f;
#pragma unroll
    for (int t = 0; t < 3; t++) { float d = xr[t] - mean; vs += d * d; }
#pragma unroll
    for (int off = 16; off > 0; off >>= 1) vs += __shfl_xor_sync(0xffffffffu, vs, off);
    if (lane == 0) ws[warp] = vs;
    __syncthreads();
    float vtot = 0.f;
#pragma unroll
    for (int w = 0; w < 8; w++) vtot += ws[w];
    const float rstd = rsqrtf(vtot * (1.0f / DD) + 1e-5f);

#pragma unroll
    for (int t = 0; t < 3; t++) {
        int i = tid + t * 256;
        o[i] = (xr[t] - mean) * rstd * g[i] + b[i];
    }
}

// ---------------- MMA flash attention ----------------
// Block = (64-query tile, head, batch); 128 threads = 4 warps; warp w owns
// rows w*16 + gid (+8). S and P live in registers (FA2 frag-identity trick).
#define QSTR 36   // half2 words per Q row (32 + 4)
#define KSTR 72   // half2 words per K/V row (64 + 8)

__global__ void __launch_bounds__(128)
fattn_k(const float* __restrict__ q, const float* __restrict__ k,
        const float* __restrict__ v, float* __restrict__ out) {
    __shared__ unsigned Qs[64 * QSTR];   // [row][d2]
    __shared__ unsigned Ks[32 * KSTR];   // [d2][key]
    __shared__ unsigned Vs[32 * KSTR];   // [k2][d]

    const int tid  = threadIdx.x;
    const int lane = tid & 31;
    const int warp = tid >> 5;
    const int gid  = lane >> 2;
    const int tig  = lane & 3;
    const int qt0 = blockIdx.x * 64;
    const int h   = blockIdx.y;
    const int b   = blockIdx.z;
    const size_t base = ((size_t)b * NTOK) * DD + (size_t)h * HDIM;

    // ---- load Q tile [64 rows][64 d] -> Qs[row][d2] ----
#pragma unroll
    for (int it = 0; it < 8; it++) {
        int idx = tid + it * 128;
        int row = idx >> 4;
        int d4  = (idx & 15) << 2;
        float4 val = *reinterpret_cast<const float4*>(&q[base + (size_t)(qt0 + row) * DD + d4]);
        *reinterpret_cast<uint2*>(&Qs[row * QSTR + (d4 >> 1)]) =
            make_uint2(packh2(val.x, val.y), packh2(val.z, val.w));
    }
    __syncthreads();

    // ---- preload Q fragments (invariant across kv tiles) ----
    unsigned qf[4][4];
    const int r0 = warp * 16 + gid;
#pragma unroll
    for (int ks = 0; ks < 4; ks++) {
        qf[ks][0] = Qs[(r0    ) * QSTR + ks * 8 + tig    ];
        qf[ks][1] = Qs[(r0 + 8) * QSTR + ks * 8 + tig    ];
        qf[ks][2] = Qs[(r0    ) * QSTR + ks * 8 + tig + 4];
        qf[ks][3] = Qs[(r0 + 8) * QSTR + ks * 8 + tig + 4];
    }

    float O[8][4];
    float m_run[2], l_run[2];
#pragma unroll
    for (int nt = 0; nt < 8; nt++)
#pragma unroll
        for (int c = 0; c < 4; c++) O[nt][c] = 0.f;
    m_run[0] = m_run[1] = -1e30f;
    l_run[0] = l_run[1] = 0.f;

    for (int kt0 = 0; kt0 < NTOK; kt0 += 64) {
        __syncthreads();   // previous tile's MMAs done before overwrite
        // K tile: [64 key][64 d] -> Ks[d2][key]
#pragma unroll
        for (int it = 0; it < 8; it++) {
            int idx = tid + it * 128;
            int row = idx >> 4;             // key
            int d4  = (idx & 15) << 2;
            float4 val = *reinterpret_cast<const float4*>(&k[base + (size_t)(kt0 + row) * DD + d4]);
            Ks[((d4 >> 1)    ) * KSTR + row] = packh2(val.x, val.y);
            Ks[((d4 >> 1) + 1) * KSTR + row] = packh2(val.z, val.w);
        }
        // V tile: [64 key][64 d] -> Vs[k2][d] (pack across key pairs)
#pragma unroll
        for (int it = 0; it < 4; it++) {
            int idx = tid + it * 128;       // 0..511
            int k2  = idx >> 4;
            int d4  = (idx & 15) << 2;
            float4 v0 = *reinterpret_cast<const float4*>(&v[base + (size_t)(kt0 + 2*k2    ) * DD + d4]);
            float4 v1 = *reinterpret_cast<const float4*>(&v[base + (size_t)(kt0 + 2*k2 + 1) * DD + d4]);
            *reinterpret_cast<uint4*>(&Vs[k2 * KSTR + d4]) =
                make_uint4(packh2(v0.x, v1.x), packh2(v0.y, v1.y),
                           packh2(v0.z, v1.z), packh2(v0.w, v1.w));
        }
        __syncthreads();

        // ---- S = Q @ K^T : 8 n-tiles of 8 keys ----
        float S[8][4];
#pragma unroll
        for (int nt = 0; nt < 8; nt++)
#pragma unroll
            for (int c = 0; c < 4; c++) S[nt][c] = 0.f;
#pragma unroll
        for (int ks = 0; ks < 4; ks++) {
#pragma unroll
            for (int nt = 0; nt < 8; nt++) {
                unsigned bf[2];
                bf[0] = Ks[(ks * 8 + tig    ) * KSTR + nt * 8 + gid];
                bf[1] = Ks[(ks * 8 + tig + 4) * KSTR + nt * 8 + gid];
                mma_f16(S[nt], qf[ks], bf);
            }
        }

        // ---- scale + mask + online softmax (rows gid, gid+8 warp-local) ----
#pragma unroll
        for (int nt = 0; nt < 8; nt++) {
            int c0 = kt0 + nt * 8 + tig * 2;
#pragma unroll
            for (int c = 0; c < 4; c++) {
                S[nt][c] *= 0.125f;
                if (c0 + (c & 1) >= NTOK) S[nt][c] = -1e30f;
            }
        }
#pragma unroll
        for (int i = 0; i < 2; i++) {
            float tm = -1e30f;
#pragma unroll
            for (int nt = 0; nt < 8; nt++)
                tm = fmaxf(tm, fmaxf(S[nt][2*i], S[nt][2*i + 1]));
            tm = fmaxf(tm, __shfl_xor_sync(0xffffffffu, tm, 1));
            tm = fmaxf(tm, __shfl_xor_sync(0xffffffffu, tm, 2));
            float mn = fmaxf(m_run[i], tm);
            float alpha = expf(m_run[i] - mn);
            float ls = 0.f;
#pragma unroll
            for (int nt = 0; nt < 8; nt++) {
                float p0 = expf(S[nt][2*i    ] - mn);
                float p1 = expf(S[nt][2*i + 1] - mn);
                S[nt][2*i] = p0; S[nt][2*i + 1] = p1;
                ls += p0 + p1;
            }
            ls += __shfl_xor_sync(0xffffffffu, ls, 1);
            ls += __shfl_xor_sync(0xffffffffu, ls, 2);
            l_run[i] = l_run[i] * alpha + ls;
            m_run[i] = mn;
#pragma unroll
            for (int nt = 0; nt < 8; nt++) {
                O[nt][2*i] *= alpha; O[nt][2*i + 1] *= alpha;
            }
        }

        // ---- O += P @ V (P from S frags, register-resident) ----
#pragma unroll
        for (int ks = 0; ks < 4; ks++) {
            unsigned pf[4];
            pf[0] = packh2(S[2*ks    ][0], S[2*ks    ][1]);
            pf[1] = packh2(S[2*ks    ][2], S[2*ks    ][3]);
            pf[2] = packh2(S[2*ks + 1][0], S[2*ks + 1][1]);
            pf[3] = packh2(S[2*ks + 1][2], S[2*ks + 1][3]);
#pragma unroll
            for (int nt = 0; nt < 8; nt++) {
                unsigned bf[2];
                bf[0] = Vs[(ks * 8 + tig    ) * KSTR + nt * 8 + gid];
                bf[1] = Vs[(ks * 8 + tig + 4) * KSTR + nt * 8 + gid];
                mma_f16(O[nt], pf, bf);
            }
        }
    }

    // ---- write output ----
#pragma unroll
    for (int i = 0; i < 2; i++) {
        int qg = qt0 + r0 + i * 8;
        if (qg >= NTOK) continue;
        float inv = 1.0f / l_run[i];
#pragma unroll
        for (int nt = 0; nt < 8; nt++) {
            float2 o2 = make_float2(O[nt][2*i] * inv, O[nt][2*i + 1] * inv);
            *reinterpret_cast<float2*>(&out[base + (size_t)qg * DD + nt * 8 + tig * 2]) = o2;
        }
    }
}

// ---------------- Head ----------------
__global__ void head_k(const float* __restrict__ cls, const float* __restrict__ hw,
                       const float* __restrict__ hb, float* __restrict__ out) {
    int idx = blockIdx.x * 256 + threadIdx.x;
    if (idx >= BB * NCLS) return;
    int b = idx / NCLS, c = idx % NCLS;
    const float* xr = &cls[b * DD];
    float acc = hb[c];
    for (int kk = 0; kk < DD; kk++) acc = fmaf(xr[kk], hw[kk * NCLS + c], acc);
    out[idx] = acc;
}

// ---------------- Launch ----------------
extern "C" void kernel_launch(void* const* d_in, const int* in_sizes, int n_in,
                              void* d_out, int out_size) {
    const float* x       = (const float*)d_in[0];
    const float* proj_w  = (const float*)d_in[1];
    const float* proj_b  = (const float*)d_in[2];
    const float* cls_emb = (const float*)d_in[3];
    const float* pos_emb = (const float*)d_in[4];
    const float* ln1_g   = (const float*)d_in[5];
    const float* ln1_b   = (const float*)d_in[6];
    const float* qw      = (const float*)d_in[7];
    const float* qb      = (const float*)d_in[8];
    const float* kw      = (const float*)d_in[9];
    const float* kb      = (const float*)d_in[10];
    const float* vw      = (const float*)d_in[11];
    const float* vb      = (const float*)d_in[12];
    const float* ow      = (const float*)d_in[13];
    const float* ob      = (const float*)d_in[14];
    const float* ln2_g   = (const float*)d_in[15];
    const float* ln2_b   = (const float*)d_in[16];
    const float* fcw     = (const float*)d_in[17];
    const float* fcb     = (const float*)d_in[18];
    const float* pw      = (const float*)d_in[19];
    const float* pb      = (const float*)d_in[20];
    const float* lnf_g   = (const float*)d_in[21];
    const float* lnf_b   = (const float*)d_in[22];
    const float* head_w  = (const float*)d_in[23];
    const float* head_b  = (const float*)d_in[24];
    float* out = (float*)d_out;
    (void)in_sizes; (void)n_in; (void)out_size;

    float *bt, *bemb, *bh, *by, *bq, *bk, *bv, *bao, *bmlp, *bcls;
    cudaGetSymbolAddress((void**)&bt,   g_t);
    cudaGetSymbolAddress((void**)&bemb, g_emb);
    cudaGetSymbolAddress((void**)&bh,   g_h);
    cudaGetSymbolAddress((void**)&by,   g_y);
    cudaGetSymbolAddress((void**)&bq,   g_q);
    cudaGetSymbolAddress((void**)&bk,   g_k);
    cudaGetSymbolAddress((void**)&bv,   g_v);
    cudaGetSymbolAddress((void**)&bao,  g_ao);
    cudaGetSymbolAddress((void**)&bmlp, g_mlp);
    cudaGetSymbolAddress((void**)&bcls, g_cls);

    // Patch embed
    patch_k<<<(MPATCH*DD + 255)/256, 256>>>(x, bt);
    gemm_f16_k<<<dim3(DD/128, MPATCH/128), 256>>>(bt, proj_w, proj_b, bemb, MPATCH, DD, DD, 0);
    assemble_k<<<(BB*NTOK*DD + 255)/256, 256>>>(bemb, cls_emb, pos_emb, bh);

    const int MB = MPAD / 128;  // 37
    const int QTILES = (NTOK + 63) / 64;  // 10
    for (int l = 0; l < LL; l++) {
        const size_t wo  = (size_t)l * DD * DD;
        const size_t wfc = (size_t)l * DD * MLPD;

        ln_k<<<MTOK, 256>>>(bh, by, ln1_g + l*DD, ln1_b + l*DD, DD);
        gemm_f16_qkv_k<<<dim3(DD/128, MB, 3), 256>>>(by, qw + wo, kw + wo, vw + wo,
                                                     qb + l*DD, kb + l*DD, vb + l*DD,
                                                     bq, bk, bv, MPAD, DD, DD);
        fattn_k<<<dim3(QTILES, NHH, BB), 128>>>(bq, bk, bv, bao);
        gemm_f16_k<<<dim3(DD/128, MB), 256>>>(bao, ow + wo, ob + l*DD, bh, MPAD, DD, DD, 1);

        ln_k<<<MTOK, 256>>>(bh, by, ln2_g + l*DD, ln2_b + l*DD, DD);
        gemm_f16_k<<<dim3(MLPD/128, MB), 256>>>(by, fcw + wfc, fcb + l*MLPD, bmlp, MPAD, MLPD, DD, 2);
        gemm_f16_k<<<dim3(DD/128, MB), 256>>>(bmlp, pw + wfc, pb + l*DD, bh, MPAD, DD, MLPD, 1);
    }

    ln_k<<<BB, 256>>>(bh, bcls, lnf_g, lnf_b, (long)NTOK * DD);
    head_k<<<(BB*NCLS + 255)/256, 256>>>(bcls, head_w, head_b, out);
}